// round 6
// baseline (speedup 1.0000x reference)
#include <cuda_runtime.h>
#include <cuda_bf16.h>
#include <cstdint>

// ---------------- problem constants ----------------
#define N_VEC   32768      // 8*4096 rows of z
#define DIM     256
#define K_CODES 8192
#define M_TILE  128
#define N_TILE  64
#define QCODES  2048                 // codes per job (quarter of codebook)
#define NT_J    (QCODES / N_TILE)    // 32 tiles per job
#define KSTEPS  (DIM / 16)           // 16 k-steps of 16
#define NJOBS   ((N_VEC / M_TILE) * 4)  // 1024

// smem: padded row stride 528 B -> conflict-free ldmatrix phases
#define ROW_B   528
#define A_BYTES (128 * ROW_B)        // 67584
#define B_BYTES (64 * ROW_B)         // 33792
#define SM_A    0
#define SM_B    (SM_A + A_BYTES)     // 3 B buffers follow
#define SM_TOTAL (SM_B + 3 * B_BYTES) // 168960

// ---------------- device scratch (static, no runtime alloc) ----------------
__device__ __nv_bfloat16 g_zb[(size_t)N_VEC * DIM];   // z in bf16
__device__ __nv_bfloat16 g_eb[(size_t)K_CODES * DIM]; // codebook in bf16
__device__ float g_normE[K_CODES];                    // sum(e^2) fp32
__device__ int4  g_top[(size_t)N_VEC * 4];            // top-4 per row per quarter

__device__ __forceinline__ uint32_t smem_to_u32(const void* p) {
    uint32_t a;
    asm("{ .reg .u64 t; cvta.to.shared.u64 t, %1; cvt.u32.u64 %0, t; }" : "=r"(a) : "l"(p));
    return a;
}

// non-volatile: lets ptxas software-pipeline loads across k-steps
__device__ __forceinline__ void ldsm_x4(uint32_t& r0, uint32_t& r1, uint32_t& r2, uint32_t& r3,
                                        uint32_t addr) {
    asm("ldmatrix.sync.aligned.m8n8.x4.shared.b16 {%0,%1,%2,%3}, [%4];"
        : "=r"(r0), "=r"(r1), "=r"(r2), "=r"(r3) : "r"(addr));
}

__device__ __forceinline__ void mma16816(float& c0, float& c1, float& c2, float& c3,
                                         uint32_t a0, uint32_t a1, uint32_t a2, uint32_t a3,
                                         uint32_t b0, uint32_t b1) {
    asm("mma.sync.aligned.m16n8k16.row.col.f32.bf16.bf16.f32 "
        "{%0,%1,%2,%3},{%4,%5,%6,%7},{%8,%9},{%0,%1,%2,%3};"
        : "+f"(c0), "+f"(c1), "+f"(c2), "+f"(c3)
        : "r"(a0), "r"(a1), "r"(a2), "r"(a3), "r"(b0), "r"(b1));
}

// top-4 insert (descending); strict > keeps earliest (lowest) index on ties
__device__ __forceinline__ void ins4(float (&S)[4], int (&I)[4], float s, int k) {
    if (s > S[3]) {
        if (s > S[1]) {
            if (s > S[0]) { S[3]=S[2];I[3]=I[2]; S[2]=S[1];I[2]=I[1]; S[1]=S[0];I[1]=I[0]; S[0]=s;I[0]=k; }
            else          { S[3]=S[2];I[3]=I[2]; S[2]=S[1];I[2]=I[1]; S[1]=s;I[1]=k; }
        } else {
            if (s > S[2]) { S[3]=S[2];I[3]=I[2]; S[2]=s;I[2]=k; }
            else          { S[3]=s;I[3]=k; }
        }
    }
}

// 64x256-bf16 B tile via cp.async: 2048 16B chunks, 256 threads x 8 iters
__device__ __forceinline__ void prefetch_B(uint32_t sm_dst, const __nv_bfloat16* src, int tid) {
    const char* g = (const char*)src;
    #pragma unroll
    for (int it = 0; it < 8; ++it) {
        int ch = tid + it * 256;
        int r = ch >> 5, c = ch & 31;
        uint32_t sa = sm_dst + r * ROW_B + c * 16;
        asm volatile("cp.async.cg.shared.global [%0], [%1], 16;"
                     :: "r"(sa), "l"(g + (size_t)r * 512 + c * 16));
    }
    asm volatile("cp.async.commit_group;" ::: "memory");
}

// ---------------- kernel 1: fp32 -> bf16 conversion ----------------
__global__ void conv_bf16_kernel(const float* __restrict__ src, int n8, int is_e) {
    int i = blockIdx.x * blockDim.x + threadIdx.x;
    if (i >= n8) return;
    const float4* s4 = (const float4*)src;
    float4 a = s4[2 * i], b = s4[2 * i + 1];
    __nv_bfloat162 p0 = __floats2bfloat162_rn(a.x, a.y);
    __nv_bfloat162 p1 = __floats2bfloat162_rn(a.z, a.w);
    __nv_bfloat162 p2 = __floats2bfloat162_rn(b.x, b.y);
    __nv_bfloat162 p3 = __floats2bfloat162_rn(b.z, b.w);
    uint4 o;
    o.x = *reinterpret_cast<uint32_t*>(&p0);
    o.y = *reinterpret_cast<uint32_t*>(&p1);
    o.z = *reinterpret_cast<uint32_t*>(&p2);
    o.w = *reinterpret_cast<uint32_t*>(&p3);
    uint4* dst = (uint4*)(is_e ? (void*)g_eb : (void*)g_zb);
    dst[i] = o;
}

// ---------------- kernel 2: ||e||^2 (validated order) ----------------
__global__ void norme_kernel(const float* __restrict__ emb) {
    int w = (blockIdx.x * blockDim.x + threadIdx.x) >> 5;
    if (w >= K_CODES) return;
    int lane = threadIdx.x & 31;
    const float4* er = (const float4*)(emb + (size_t)w * DIM);
    float4 a = er[lane * 2], b = er[lane * 2 + 1];
    float s = a.x*a.x + a.y*a.y + a.z*a.z + a.w*a.w
            + b.x*b.x + b.y*b.y + b.z*b.z + b.w*b.w;
    #pragma unroll
    for (int o = 16; o > 0; o >>= 1) s += __shfl_xor_sync(0xffffffffu, s, o);
    if (lane == 0) g_normE[w] = s;
}

// ---------------- kernel 3: job-based bf16 HMMA GEMM + register top-4 ----------------
// job = (m-tile of 128 rows) x (codebook quarter of 2048 codes); grid = 1024
__global__ void __launch_bounds__(256, 1) vq_gemm_kernel() {
    extern __shared__ char smem[];
    const uint32_t sb = smem_to_u32(smem);
    const int tid  = threadIdx.x;
    const int wid  = tid >> 5;
    const int lane = tid & 31;
    const int m0 = (blockIdx.x >> 2) * M_TILE;
    const int q  = blockIdx.x & 3;
    const __nv_bfloat16* ebq = g_eb + (size_t)q * QCODES * DIM;

    // warp tile: m16 x n64 (8 warps cover M=128)
    const int warp_m = wid * 16;
    const int quad = lane >> 3, within = lane & 7;
    const uint32_t offA = (uint32_t)((warp_m + ((quad & 1) ? 8 : 0) + within) * ROW_B
                                     + ((quad & 2) ? 8 : 0) * 2);
    uint32_t offB[4];
    #pragma unroll
    for (int p = 0; p < 4; ++p)
        offB[p] = (uint32_t)((p * 16 + ((quad & 2) ? 8 : 0) + within) * ROW_B
                             + ((quad & 1) ? 8 : 0) * 2);

    // initial: A tile + B0 (group 0), B1 (group 1)
    {
        const char* g = (const char*)(g_zb + (size_t)m0 * DIM);
        #pragma unroll
        for (int it = 0; it < 16; ++it) {
            int ch = tid + it * 256;
            int r = ch >> 5, c = ch & 31;
            uint32_t sa = sb + SM_A + r * ROW_B + c * 16;
            asm volatile("cp.async.cg.shared.global [%0], [%1], 16;"
                         :: "r"(sa), "l"(g + (size_t)r * 512 + c * 16));
        }
        const char* gb = (const char*)ebq;
        #pragma unroll
        for (int it = 0; it < 8; ++it) {
            int ch = tid + it * 256;
            int r = ch >> 5, c = ch & 31;
            uint32_t sa = sb + SM_B + r * ROW_B + c * 16;
            asm volatile("cp.async.cg.shared.global [%0], [%1], 16;"
                         :: "r"(sa), "l"(gb + (size_t)r * 512 + c * 16));
        }
        asm volatile("cp.async.commit_group;" ::: "memory");
        prefetch_B(sb + SM_B + B_BYTES, ebq + (size_t)N_TILE * DIM, tid);
    }

    // two row-slots per thread: rows warp_m + (lane>>2) and +8
    float tS[2][4]; int tI[2][4];
    #pragma unroll
    for (int r = 0; r < 2; ++r)
        #pragma unroll
        for (int j = 0; j < 4; ++j) { tS[r][j] = -3.4e38f; tI[r][j] = 0; }

    int buf = 0;
    for (int t = 0; t < NT_J; ++t) {
        asm volatile("cp.async.wait_group 1;" ::: "memory");
        __syncthreads();

        if (t + 2 < NT_J) {
            int nb3 = buf + 2; if (nb3 >= 3) nb3 -= 3;
            prefetch_B(sb + SM_B + nb3 * B_BYTES, ebq + (size_t)(t + 2) * N_TILE * DIM, tid);
        }

        const uint32_t bufA = sb + SM_A;
        const uint32_t bufB = sb + SM_B + buf * B_BYTES;

        float acc[8][4];
        #pragma unroll
        for (int nb = 0; nb < 8; ++nb)
            #pragma unroll
            for (int e = 0; e < 4; ++e) acc[nb][e] = 0.f;

        #pragma unroll
        for (int ks = 0; ks < KSTEPS; ++ks) {
            const uint32_t kb = (uint32_t)(ks * 32);   // 16 bf16 = 32 B
            uint32_t a0, a1, a2, a3;
            ldsm_x4(a0, a1, a2, a3, bufA + offA + kb);
            #pragma unroll
            for (int p = 0; p < 4; ++p) {
                uint32_t b0, b1, b2, b3;
                ldsm_x4(b0, b1, b2, b3, bufB + offB[p] + kb);
                mma16816(acc[2*p][0],   acc[2*p][1],   acc[2*p][2],   acc[2*p][3],
                         a0, a1, a2, a3, b0, b1);
                mma16816(acc[2*p+1][0], acc[2*p+1][1], acc[2*p+1][2], acc[2*p+1][3],
                         a0, a1, a2, a3, b2, b3);
            }
        }

        // fold into per-thread top-4 (indices from standard m16n8 C layout)
        const int colbase = q * QCODES + t * N_TILE + (lane & 3) * 2;
        #pragma unroll
        for (int nb = 0; nb < 8; ++nb) {
            int c = colbase + nb * 8;
            float m01 = fmaxf(acc[nb][0], acc[nb][1]);
            if (m01 > tS[0][3]) {
                ins4(tS[0], tI[0], acc[nb][0], c);
                ins4(tS[0], tI[0], acc[nb][1], c + 1);
            }
            float m23 = fmaxf(acc[nb][2], acc[nb][3]);
            if (m23 > tS[1][3]) {
                ins4(tS[1], tI[1], acc[nb][2], c);
                ins4(tS[1], tI[1], acc[nb][3], c + 1);
            }
        }

        if (++buf == 3) buf = 0;
    }

    // merge top-4 across the 4 lanes of each quad (they share the same 2 rows)
    #pragma unroll
    for (int st = 1; st <= 2; st <<= 1) {
        #pragma unroll
        for (int r = 0; r < 2; ++r) {
            float os[4]; int oi[4];
            #pragma unroll
            for (int j = 0; j < 4; ++j) {
                os[j] = __shfl_xor_sync(0xffffffffu, tS[r][j], st);
                oi[j] = __shfl_xor_sync(0xffffffffu, tI[r][j], st);
            }
            #pragma unroll
            for (int j = 0; j < 4; ++j) ins4(tS[r], tI[r], os[j], oi[j]);
        }
    }
    if ((lane & 3) == 0) {
        int r0 = warp_m + (lane >> 2);
        g_top[(size_t)(m0 + r0) * 4 + q]     = make_int4(tI[0][0], tI[0][1], tI[0][2], tI[0][3]);
        g_top[(size_t)(m0 + r0 + 8) * 4 + q] = make_int4(tI[1][0], tI[1][1], tI[1][2], tI[1][3]);
    }
}

// ---------------- kernel 4: exact fp32 re-rank of 16 candidates + gather ----------------
// dist_k = fl( fl(A - fl(2*d_k)) + C_k ); d serial ascending fmaf; lowest-index ties.
__global__ void __launch_bounds__(256) vq_pick_kernel(const float* __restrict__ z,
                                                      const float* __restrict__ emb,
                                                      float* __restrict__ out) {
    int w = (blockIdx.x * blockDim.x + threadIdx.x) >> 5;
    if (w >= N_VEC) return;
    int lane = threadIdx.x & 31;
    const float4* zr4 = (const float4*)(z + (size_t)w * DIM);

    float A = 0.f;
    if (lane == 0) {
        float a = 0.f;
        for (int i = 0; i < 64; ++i) {
            float4 v = zr4[i];
            a = __fadd_rn(a, __fmul_rn(v.x, v.x));
            a = __fadd_rn(a, __fmul_rn(v.y, v.y));
            a = __fadd_rn(a, __fmul_rn(v.z, v.z));
            a = __fadd_rn(a, __fmul_rn(v.w, v.w));
        }
        A = a;
    }
    A = __shfl_sync(0xffffffffu, A, 0);

    int myk = 0x7fffffff;
    if (lane < 16) {
        int4 cq = g_top[(size_t)w * 4 + (lane >> 2)];
        int sel = lane & 3;
        myk = (sel == 0) ? cq.x : (sel == 1) ? cq.y : (sel == 2) ? cq.z : cq.w;
    }

    float v = 3.4e38f;
    if (lane < 16) {
        const float4* er4 = (const float4*)(emb + (size_t)myk * DIM);
        float acc = 0.f;   // serial ascending fmaf (validated vs reference)
        for (int i = 0; i < 64; ++i) {
            float4 zv = zr4[i];
            float4 ev = er4[i];
            acc = fmaf(zv.x, ev.x, acc);
            acc = fmaf(zv.y, ev.y, acc);
            acc = fmaf(zv.z, ev.z, acc);
            acc = fmaf(zv.w, ev.w, acc);
        }
        float t = __fsub_rn(A, __fmul_rn(2.0f, acc));
        v = __fadd_rn(t, g_normE[myk]);
    }

    // lowest-index argmin across 16 candidate lanes
    float bv = v; int bk = myk;
    #pragma unroll
    for (int c = 1; c < 16; ++c) {
        float ov = __shfl_sync(0xffffffffu, v, c);
        int   ok = __shfl_sync(0xffffffffu, myk, c);
        if (ov < bv || (ov == bv && ok < bk)) { bv = ov; bk = ok; }
    }
    bk = __shfl_sync(0xffffffffu, bk, 0);

    const float4* er4 = (const float4*)(emb + (size_t)bk * DIM);
    float4* o4 = (float4*)(out + (size_t)w * DIM);
    o4[lane]      = er4[lane];
    o4[lane + 32] = er4[lane + 32];
}

// ---------------- launch ----------------
extern "C" void kernel_launch(void* const* d_in, const int* in_sizes, int n_in,
                              void* d_out, int out_size) {
    const float* z   = (const float*)d_in[0];
    const float* emb = (const float*)d_in[1];
    if (n_in >= 2 && in_sizes[0] == K_CODES * DIM && in_sizes[1] == N_VEC * DIM) {
        const float* t = z; z = emb; emb = t;   // defensive: fix input ordering
    }
    float* out = (float*)d_out;

    conv_bf16_kernel<<<(N_VEC * DIM / 8 + 255) / 256, 256>>>(z,   N_VEC * DIM / 8,   0);
    conv_bf16_kernel<<<(K_CODES * DIM / 8 + 255) / 256, 256>>>(emb, K_CODES * DIM / 8, 1);
    norme_kernel<<<(K_CODES * 32 + 255) / 256, 256>>>(emb);

    cudaFuncSetAttribute(vq_gemm_kernel, cudaFuncAttributeMaxDynamicSharedMemorySize, SM_TOTAL);
    vq_gemm_kernel<<<NJOBS, 256, SM_TOTAL>>>();

    vq_pick_kernel<<<(N_VEC * 32 + 255) / 256, 256>>>(z, emb, out);
}